// round 15
// baseline (speedup 1.0000x reference)
#include <cuda_runtime.h>
#include <cuda_bf16.h>
#include <math.h>
#include <stdint.h>

#define TT 512
#define BB 64
#define DD 512
#define HH 512
#define DH 1024
#define NG 2048          // 4*H gate rows (packed: row = hcol*4 + gate)
#define NPRE 2560        // gates + residual rows (residual: 2048 + hcol)
#define NCTA 128
#define NTB (TT * BB)    // 32768 GEMM columns

// ---------------- scratch (device globals; no allocations) ----------------
__device__ __nv_bfloat16 g_Wxhi[(size_t)NPRE * DD];
__device__ __nv_bfloat16 g_Wxlo[(size_t)NPRE * DD];
__device__ __nv_bfloat16 g_Whhi[(size_t)NG * HH];
__device__ __nv_bfloat16 g_Whlo[(size_t)NG * HH];
__device__ __nv_bfloat16 g_xhi[(size_t)NTB * DD];
__device__ __nv_bfloat16 g_xlo[(size_t)NTB * DD];
__device__ float g_bias[NPRE];
__device__ float g_pre[(size_t)NTB * NPRE];      // [col = t*64+b][packed_n]
__device__ __nv_bfloat16 g_hhi[2 * BB * HH];     // h state, double-buffered
__device__ __nv_bfloat16 g_hlo[2 * BB * HH];
__device__ unsigned g_cnt[4 * 4 * 32];           // monotone counters [bblk][quarter], 128B apart

// ---------------- mma / ldmatrix helpers (baseline PTX, sm_80+) ----------------
__device__ __forceinline__ uint32_t smem_u32(const void* p) {
    uint32_t a;
    asm("{ .reg .u64 t; cvta.to.shared.u64 t, %1; cvt.u32.u64 %0, t; }" : "=r"(a) : "l"(p));
    return a;
}
__device__ __forceinline__ void ldsm4(uint32_t addr, uint32_t* r) {
    asm volatile("ldmatrix.sync.aligned.m8n8.x4.shared.b16 {%0,%1,%2,%3}, [%4];"
                 : "=r"(r[0]), "=r"(r[1]), "=r"(r[2]), "=r"(r[3]) : "r"(addr));
}
__device__ __forceinline__ void mma16816(float* d, const uint32_t* a, const uint32_t* b) {
    asm volatile("mma.sync.aligned.m16n8k16.row.col.f32.bf16.bf16.f32 "
                 "{%0,%1,%2,%3}, {%4,%5,%6,%7}, {%8,%9}, {%0,%1,%2,%3};"
                 : "+f"(d[0]), "+f"(d[1]), "+f"(d[2]), "+f"(d[3])
                 : "r"(a[0]), "r"(a[1]), "r"(a[2]), "r"(a[3]), "r"(b[0]), "r"(b[1]));
}
__device__ __forceinline__ void cp_async16(uint32_t dst, const void* src) {
    asm volatile("cp.async.cg.shared.global [%0], [%1], 16;" :: "r"(dst), "l"(src) : "memory");
}
__device__ __forceinline__ float fast_sigmoid(float x) {
    return __fdividef(1.f, 1.f + __expf(-x));
}
__device__ __forceinline__ float fast_tanh(float x) {
    return 1.f - __fdividef(2.f, __expf(2.f * x) + 1.f);
}
// single-word relaxed spin + final acquire
__device__ __forceinline__ void cnt_wait(const unsigned* p, unsigned target) {
    unsigned v;
    do {
        asm volatile("ld.relaxed.gpu.global.u32 %0, [%1];" : "=r"(v) : "l"(p) : "memory");
    } while (v < target);
    asm volatile("ld.acquire.gpu.global.u32 %0, [%1];" : "=r"(v) : "l"(p) : "memory");
}

// ---------------- pack weights + convert x (fused) ----------------
__global__ void pack_kernel(const float* __restrict__ x,
                            const float* __restrict__ Wf, const float* __restrict__ bf,
                            const float* __restrict__ Wi, const float* __restrict__ bi,
                            const float* __restrict__ Wg, const float* __restrict__ bg,
                            const float* __restrict__ Wo, const float* __restrict__ bo,
                            const float* __restrict__ Wr, const float* __restrict__ br) {
    int idx = blockIdx.x * blockDim.x + threadIdx.x;
    int stride = gridDim.x * blockDim.x;
    for (int i = idx; i < NPRE * DD; i += stride) {
        int n = i / DD, d = i - n * DD;
        float v;
        if (n < NG) {
            int hcol = n >> 2, gate = n & 3;
            const float* W = (gate == 0) ? Wf : (gate == 1) ? Wi : (gate == 2) ? Wg : Wo;
            v = W[hcol * DH + d];
        } else {
            v = Wr[(n - NG) * DD + d];
        }
        __nv_bfloat16 hi = __float2bfloat16_rn(v);
        g_Wxhi[i] = hi;
        g_Wxlo[i] = __float2bfloat16_rn(v - __bfloat162float(hi));
    }
    for (int i = idx; i < NG * HH; i += stride) {
        int n = i / HH, k = i - n * HH;
        int hcol = n >> 2, gate = n & 3;
        const float* W = (gate == 0) ? Wf : (gate == 1) ? Wi : (gate == 2) ? Wg : Wo;
        float v = W[hcol * DH + DD + k];
        __nv_bfloat16 hi = __float2bfloat16_rn(v);
        g_Whhi[i] = hi;
        g_Whlo[i] = __float2bfloat16_rn(v - __bfloat162float(hi));
    }
    for (int i = idx; i < NPRE; i += stride) {
        float v;
        if (i < NG) {
            int hcol = i >> 2, gate = i & 3;
            v = (gate == 0) ? bf[hcol] : (gate == 1) ? bi[hcol] : (gate == 2) ? bg[hcol] : bo[hcol];
        } else {
            v = br[i - NG];
        }
        g_bias[i] = v;
    }
    // reset arrival counters (device globals persist across graph replays)
    for (int i = idx; i < 4 * 4 * 32; i += stride) g_cnt[i] = 0u;
    // x -> bf16 hi/lo
    for (size_t i = idx; i < (size_t)NTB * DD; i += stride) {
        float v = x[i];
        __nv_bfloat16 hi = __float2bfloat16_rn(v);
        g_xhi[i] = hi;
        g_xlo[i] = __float2bfloat16_rn(v - __bfloat162float(hi));
    }
}

// ---------------- pre-activation GEMM (HMMA, split bf16), 128x128 tiles ----------------
#define P_ROW 40                         // padded row (bf16 elems) -> 80B stride
#define P_HALF (128 * P_ROW * 2)         // 10240 B per operand-half per stage
#define P_STAGE (4 * P_HALF)             // 40960 B
#define P_SMEM (2 * P_STAGE)             // 81920 B
__global__ void __launch_bounds__(512) pre_gemm_mma() {
    extern __shared__ char sm[];
    const uint32_t smb = smem_u32(sm);
    const int tid = threadIdx.x;
    const int wid = tid >> 5, lane = tid & 31;
    const int mw = wid & 3, nw = wid >> 2;          // warp tile: m32 x n32
    const int mbase = blockIdx.x * 128;             // 20 m-tiles
    const int nbase = blockIdx.y * 128;             // 256 n-tiles

    const int o = tid >> 7, r = tid & 127;
    const __nv_bfloat16* gsrc =
        (o == 0) ? g_Wxhi + (size_t)(mbase + r) * DD :
        (o == 1) ? g_Wxlo + (size_t)(mbase + r) * DD :
        (o == 2) ? g_xhi + (size_t)(nbase + r) * DD :
                   g_xlo + (size_t)(nbase + r) * DD;
    const uint32_t sdst = smb + o * P_HALF + r * 80;

    const int aRow = mw * 32 + ((lane >> 3) & 1) * 8 + (lane & 7);
    const uint32_t aOff = (uint32_t)(aRow * 80 + ((lane >> 4) * 8) * 2);
    const int g8 = lane >> 3;
    uint32_t bOff[2];
#pragma unroll
    for (int pair = 0; pair < 2; pair++) {
        int nRow = nw * 32 + (pair * 2 + (g8 >> 1)) * 8 + (lane & 7);
        bOff[pair] = (uint32_t)(nRow * 80 + ((g8 & 1) * 8) * 2);
    }

    float acc[2][4][4];
#pragma unroll
    for (int i = 0; i < 2; i++)
#pragma unroll
        for (int j = 0; j < 4; j++)
#pragma unroll
            for (int q = 0; q < 4; q++) acc[i][j][q] = 0.f;

    uint4 pf[4];
    auto gload = [&](int chunk) {
        const __nv_bfloat16* p = gsrc + chunk * 32;
#pragma unroll
        for (int j = 0; j < 4; j++) pf[j] = *(const uint4*)(p + j * 8);
    };
    auto sstore = [&](int buf) {
        uint32_t d = sdst + buf * P_STAGE;
#pragma unroll
        for (int j = 0; j < 4; j++)
            *(uint4*)(sm + (d - smb) + j * 16) = pf[j];
    };
    auto do_mma = [&](int buf) {
        uint32_t base = smb + buf * P_STAGE;
#pragma unroll
        for (int kt = 0; kt < 2; kt++) {
            uint32_t ko = kt * 32;
            uint32_t aHi[2][4], aLo[2][4], bHi[4][2], bLo[4][2];
#pragma unroll
            for (int mt = 0; mt < 2; mt++) {
                ldsm4(base + 0 * P_HALF + aOff + mt * 16 * 80 + ko, aHi[mt]);
                ldsm4(base + 1 * P_HALF + aOff + mt * 16 * 80 + ko, aLo[mt]);
            }
#pragma unroll
            for (int pair = 0; pair < 2; pair++) {
                uint32_t t4[4];
                ldsm4(base + 2 * P_HALF + bOff[pair] + ko, t4);
                bHi[pair * 2][0] = t4[0]; bHi[pair * 2][1] = t4[1];
                bHi[pair * 2 + 1][0] = t4[2]; bHi[pair * 2 + 1][1] = t4[3];
                ldsm4(base + 3 * P_HALF + bOff[pair] + ko, t4);
                bLo[pair * 2][0] = t4[0]; bLo[pair * 2][1] = t4[1];
                bLo[pair * 2 + 1][0] = t4[2]; bLo[pair * 2 + 1][1] = t4[3];
            }
#pragma unroll
            for (int mt = 0; mt < 2; mt++)
#pragma unroll
                for (int nt = 0; nt < 4; nt++) {
                    mma16816(acc[mt][nt], aHi[mt], bHi[nt]);
                    mma16816(acc[mt][nt], aHi[mt], bLo[nt]);
                    mma16816(acc[mt][nt], aLo[mt], bHi[nt]);
                }
        }
    };

    gload(0); sstore(0);
    gload(1);
    __syncthreads();
    for (int c = 0; c < 16; c++) {
        if (c + 1 < 16) sstore((c + 1) & 1);
        if (c + 2 < 16) gload(c + 2);
        do_mma(c & 1);
        __syncthreads();
    }

    float* smf = (float*)sm;
#pragma unroll
    for (int mt = 0; mt < 2; mt++)
#pragma unroll
        for (int nt = 0; nt < 4; nt++) {
            int c0 = nw * 32 + nt * 8 + 2 * (lane & 3);
            int r0 = mw * 32 + mt * 16 + (lane >> 2);
            smf[c0 * 132 + r0] = acc[mt][nt][0];
            smf[(c0 + 1) * 132 + r0] = acc[mt][nt][1];
            smf[c0 * 132 + r0 + 8] = acc[mt][nt][2];
            smf[(c0 + 1) * 132 + r0 + 8] = acc[mt][nt][3];
        }
    __syncthreads();
#pragma unroll
    for (int j = 0; j < 8; j++) {
        int idx = j * 512 + tid;
        int c = idx >> 5, seg = idx & 31;
        float4 v = *(const float4*)(smf + c * 132 + seg * 4);
        float4 bv = *(const float4*)&g_bias[mbase + seg * 4];
        v.x += bv.x; v.y += bv.y; v.z += bv.z; v.w += bv.w;
        *(float4*)&g_pre[(size_t)(nbase + c) * NPRE + mbase + seg * 4] = v;
    }
}

// ---------------- persistent LSTM recurrence (HMMA, W resident in smem) ----------------
#define R_WROW 520                       // padded k (bf16) -> 1040B stride
#define R_OWHI 0
#define R_OWLO (64 * R_WROW * 2)         // 66560
#define R_OBHI (2 * 64 * R_WROW * 2)     // 133120
#define R_OBLO (R_OBHI + 16 * R_WROW * 2)
#define R_OACC (R_OBHI + 2 * 16 * R_WROW * 2)
#define R_SMEM (R_OACC + 64 * 17 * 4)    // sAcc[64 rows][16 b] pitch 17
__global__ void __launch_bounds__(256) lstm_persistent(float* __restrict__ out) {
    extern __shared__ char sm[];
    const uint32_t smb = smem_u32(sm);
    const int tid = threadIdx.x;
    const int wid = tid >> 5, lane = tid & 31;
    const int cta = blockIdx.x;
    const int rb = cta & 31;             // 16 hcols: rb*16..
    const int bblk = cta >> 5;           // group: 16 b = bblk*16..
    const int mw = wid & 3;              // m16 tile within 64 rows
    const int nw = wid >> 2;             // b8 tile within 16 b
    const unsigned* cnt = &g_cnt[bblk * 4 * 32];
    unsigned* mycnt = &g_cnt[(bblk * 4 + (rb >> 3)) * 32];

    // ---- load resident W slice (packed rows rb*64..+63), full k ----
    for (int i = tid; i < 64 * 64 * 2; i += 256) {
        int hf = i >> 12;
        int rem = i & 4095;
        int r = rem >> 6, s = rem & 63;
        const __nv_bfloat16* src = (hf ? g_Whlo : g_Whhi) + (size_t)(rb * 64 + r) * HH + s * 8;
        *(uint4*)(sm + (hf ? R_OWLO : R_OWHI) + r * (R_WROW * 2) + s * 16) = *(const uint4*)src;
    }

    // ldmatrix lane offsets
    const int aRow = mw * 16 + ((lane >> 3) & 1) * 8 + (lane & 7);
    const uint32_t aOff = (uint32_t)(aRow * (R_WROW * 2) + ((lane >> 4) * 8) * 2);
    const int bRow = nw * 8 + (lane & 7);            // ldsm4 over k32
    const uint32_t bOff = (uint32_t)(bRow * (R_WROW * 2) + ((lane >> 3) * 8) * 2);

    // cell-update lane mapping: hcol contiguous within warp (coalesced I/O)
    const int hc_l = lane & 15;                      // 0..15
    const int bsel = wid * 2 + (lane >> 4);          // 0..15
    const int hcol = rb * 16 + hc_l;
    const int b = bblk * 16 + bsel;
    float* sAcc = (float*)(sm + R_OACC);             // [r 0..63][b 0..15], pitch 17

    float cst = 0.f;
    float hlast = 0.f;

    float4 pg;
    float rv;
    {
        const size_t cb = (size_t)(0 * BB + b) * NPRE;
        pg = __ldcs((const float4*)&g_pre[cb + hcol * 4]);
        rv = __ldcs(&g_pre[cb + NG + hcol]);
    }

    __syncthreads();

    for (int t = 0; t < TT; t++) {
        float gv0 = 0.f, gv1 = 0.f, gv2 = 0.f, gv3 = 0.f;
        if (t > 0) {
            const int rbuf = (t - 1) & 1;
            const unsigned target = (unsigned)t * 8u;
            const __nv_bfloat16* hhiB = g_hhi + rbuf * BB * HH;
            const __nv_bfloat16* hloB = g_hlo + rbuf * BB * HH;

            // stage chunk q (k = q*128..): 512 x 16B; produced by rb quarter q
            auto stage_chunk = [&](int q) {
#pragma unroll
                for (int j = 0; j < 2; j++) {
                    int i = tid + j * 256;           // 0..511
                    int hf = i >> 8;
                    int rem = i & 255;
                    int r = rem >> 4, s = (rem & 15) + q * 16;
                    const void* src = (const void*)((hf ? hloB : hhiB) +
                                                    (size_t)(bblk * 16 + r) * HH + s * 8);
                    cp_async16(smb + (hf ? R_OBLO : R_OBHI) + r * (R_WROW * 2) + s * 16, src);
                }
                asm volatile("cp.async.commit_group;" ::: "memory");
            };

            float aA0[4] = {}, aB0[4] = {}, aC0[4] = {};
            float aA1[4] = {}, aB1[4] = {}, aC1[4] = {};

            // mma section sec covers kt2 = sec*4 .. sec*4+3 (k = sec*128 ..)
            auto mma_sect = [&](int sec) {
#pragma unroll
                for (int u = 0; u < 4; u++) {
                    uint32_t ko = (uint32_t)(sec * 4 + u) * 64;
                    uint32_t aHi0[4], aHi1[4], aLo0[4], aLo1[4], bH[4], bL[4];
                    ldsm4(smb + R_OWHI + aOff + ko, aHi0);
                    ldsm4(smb + R_OWHI + aOff + ko + 32, aHi1);
                    ldsm4(smb + R_OWLO + aOff + ko, aLo0);
                    ldsm4(smb + R_OWLO + aOff + ko + 32, aLo1);
                    ldsm4(smb + R_OBHI + bOff + ko, bH);
                    ldsm4(smb + R_OBLO + bOff + ko, bL);
                    mma16816(aA0, aHi0, bH);
                    mma16816(aB0, aHi0, bL);
                    mma16816(aC0, aLo0, bH);
                    mma16816(aA1, aHi1, bH + 2);
                    mma16816(aB1, aHi1, bL + 2);
                    mma16816(aC1, aLo1, bH + 2);
                }
            };

            // 4-deep pipeline: poll/stage runs 2 chunks ahead of mma
            cnt_wait(cnt + 0 * 32, target); stage_chunk(0);
            cnt_wait(cnt + 1 * 32, target); stage_chunk(1);
            asm volatile("cp.async.wait_group 1;" ::: "memory");
            __syncthreads();
            mma_sect(0);
            cnt_wait(cnt + 2 * 32, target); stage_chunk(2);
            asm volatile("cp.async.wait_group 1;" ::: "memory");
            __syncthreads();
            mma_sect(1);
            cnt_wait(cnt + 3 * 32, target); stage_chunk(3);
            asm volatile("cp.async.wait_group 1;" ::: "memory");
            __syncthreads();
            mma_sect(2);
            asm volatile("cp.async.wait_group 0;" ::: "memory");
            __syncthreads();
            mma_sect(3);

            {
                int r0 = mw * 16 + (lane >> 2);
                int c0 = nw * 8 + 2 * (lane & 3);
                sAcc[r0 * 17 + c0]           = aA0[0] + aB0[0] + aC0[0] + aA1[0] + aB1[0] + aC1[0];
                sAcc[r0 * 17 + c0 + 1]       = aA0[1] + aB0[1] + aC0[1] + aA1[1] + aB1[1] + aC1[1];
                sAcc[(r0 + 8) * 17 + c0]     = aA0[2] + aB0[2] + aC0[2] + aA1[2] + aB1[2] + aC1[2];
                sAcc[(r0 + 8) * 17 + c0 + 1] = aA0[3] + aB0[3] + aC0[3] + aA1[3] + aB1[3] + aC1[3];
            }
            __syncthreads();
            gv0 = sAcc[(hc_l * 4 + 0) * 17 + bsel];
            gv1 = sAcc[(hc_l * 4 + 1) * 17 + bsel];
            gv2 = sAcc[(hc_l * 4 + 2) * 17 + bsel];
            gv3 = sAcc[(hc_l * 4 + 3) * 17 + bsel];
        }

        // consume pg/rv, then immediately prefetch t+1 (overlaps transcendentals + publish)
        float fp = pg.x + gv0, ip = pg.y + gv1, gp = pg.z + gv2, op = pg.w + gv3;
        float rvc = rv;
        if (t + 1 < TT) {
            const size_t cb = (size_t)((t + 1) * BB + b) * NPRE;
            pg = __ldcs((const float4*)&g_pre[cb + hcol * 4]);
            rv = __ldcs(&g_pre[cb + NG + hcol]);
        }

        float f = fast_sigmoid(fp);
        float ii = fast_sigmoid(ip);
        float gg = fast_tanh(gp);
        float oo = fast_sigmoid(op);
        cst = f * cst + ii * gg;
        float h = oo * fast_tanh(cst) + rvc;
        hlast = h;

        const int wbuf = t & 1;
        __nv_bfloat16 hhi = __float2bfloat16_rn(h);
        __nv_bfloat16 hlo = __float2bfloat16_rn(h - __bfloat162float(hhi));
        {
            unsigned short uhi = *(unsigned short*)&hhi;
            unsigned short ulo = *(unsigned short*)&hlo;
            asm volatile("st.global.cg.u16 [%0], %1;"
                         :: "l"(&g_hhi[wbuf * BB * HH + b * HH + hcol]), "h"(uhi) : "memory");
            asm volatile("st.global.cg.u16 [%0], %1;"
                         :: "l"(&g_hlo[wbuf * BB * HH + b * HH + hcol]), "h"(ulo) : "memory");
        }

        if (t + 1 < TT) {
            __syncthreads();             // order this CTA's h stores before the release
            if (tid == 0) {
                unsigned d;
                asm volatile("atom.release.gpu.global.add.u32 %0, [%1], 1;"
                             : "=r"(d) : "l"(mycnt) : "memory");
            }
            // off-critical-path:
            out[(size_t)t * BB * HH + (size_t)b * HH + hcol] = h;
        } else {
            out[(size_t)t * BB * HH + (size_t)b * HH + hcol] = h;
        }
    }

    out[(size_t)TT * BB * HH + (size_t)b * HH + hcol] = hlast;
    out[(size_t)TT * BB * HH + BB * HH + (size_t)b * HH + hcol] = cst;
}

extern "C" void kernel_launch(void* const* d_in, const int* in_sizes, int n_in,
                              void* d_out, int out_size) {
    const float* x  = (const float*)d_in[0];
    const float* Wf = (const float*)d_in[1];
    const float* bf = (const float*)d_in[2];
    const float* Wi = (const float*)d_in[3];
    const float* bi = (const float*)d_in[4];
    const float* Wg = (const float*)d_in[5];
    const float* bg = (const float*)d_in[6];
    const float* Wo = (const float*)d_in[7];
    const float* bo = (const float*)d_in[8];
    const float* Wr = (const float*)d_in[9];
    const float* br = (const float*)d_in[10];
    float* out = (float*)d_out;

    static int inited = 0;
    if (!inited) {
        cudaFuncSetAttribute(pre_gemm_mma, cudaFuncAttributeMaxDynamicSharedMemorySize, P_SMEM);
        cudaFuncSetAttribute(lstm_persistent, cudaFuncAttributeMaxDynamicSharedMemorySize, R_SMEM);
        inited = 1;
    }

    pack_kernel<<<512, 256>>>(x, Wf, bf, Wi, bi, Wg, bg, Wo, bo, Wr, br);
    pre_gemm_mma<<<dim3(NPRE / 128, NTB / 128), 512, P_SMEM>>>();
    lstm_persistent<<<NCTA, 256, R_SMEM>>>(out);
}

// round 17
// speedup vs baseline: 1.0934x; 1.0934x over previous
#include <cuda_runtime.h>
#include <cuda_bf16.h>
#include <math.h>
#include <stdint.h>

#define TT 512
#define BB 64
#define DD 512
#define HH 512
#define DH 1024
#define NG 2048          // 4*H gate rows (packed: row = hcol*4 + gate)
#define NPRE 2560        // gates + residual rows (residual: 2048 + hcol)
#define NCTA 128
#define NTB (TT * BB)    // 32768 GEMM columns

// ---------------- scratch (device globals; no allocations) ----------------
__device__ __nv_bfloat16 g_Wxhi[(size_t)NPRE * DD];
__device__ __nv_bfloat16 g_Wxlo[(size_t)NPRE * DD];
__device__ __nv_bfloat16 g_Whhi[(size_t)NG * HH];
__device__ __nv_bfloat16 g_Whlo[(size_t)NG * HH];
__device__ __nv_bfloat16 g_xhi[(size_t)NTB * DD];
__device__ __nv_bfloat16 g_xlo[(size_t)NTB * DD];
__device__ float g_bias[NPRE];
__device__ float g_pre[(size_t)NTB * NPRE];      // [col = t*64+b][packed_n]
__device__ __nv_bfloat16 g_hhi[2 * BB * HH];     // h state, double-buffered
__device__ __nv_bfloat16 g_hlo[2 * BB * HH];
__device__ unsigned g_cnt[4 * 2 * 32];           // monotone arrival counters [bblk][half], 128B apart

// ---------------- mma / ldmatrix helpers (baseline PTX, sm_80+) ----------------
__device__ __forceinline__ uint32_t smem_u32(const void* p) {
    uint32_t a;
    asm("{ .reg .u64 t; cvta.to.shared.u64 t, %1; cvt.u32.u64 %0, t; }" : "=r"(a) : "l"(p));
    return a;
}
__device__ __forceinline__ void ldsm4(uint32_t addr, uint32_t* r) {
    asm volatile("ldmatrix.sync.aligned.m8n8.x4.shared.b16 {%0,%1,%2,%3}, [%4];"
                 : "=r"(r[0]), "=r"(r[1]), "=r"(r[2]), "=r"(r[3]) : "r"(addr));
}
__device__ __forceinline__ void mma16816(float* d, const uint32_t* a, const uint32_t* b) {
    asm volatile("mma.sync.aligned.m16n8k16.row.col.f32.bf16.bf16.f32 "
                 "{%0,%1,%2,%3}, {%4,%5,%6,%7}, {%8,%9}, {%0,%1,%2,%3};"
                 : "+f"(d[0]), "+f"(d[1]), "+f"(d[2]), "+f"(d[3])
                 : "r"(a[0]), "r"(a[1]), "r"(a[2]), "r"(a[3]), "r"(b[0]), "r"(b[1]));
}
__device__ __forceinline__ void cp_async16(uint32_t dst, const void* src) {
    asm volatile("cp.async.cg.shared.global [%0], [%1], 16;" :: "r"(dst), "l"(src) : "memory");
}
__device__ __forceinline__ float fast_sigmoid(float x) {
    return __fdividef(1.f, 1.f + __expf(-x));
}
__device__ __forceinline__ float fast_tanh(float x) {
    return 1.f - __fdividef(2.f, __expf(2.f * x) + 1.f);
}
// single-word acquire spin: the satisfying load IS the acquire (no extra round trip)
__device__ __forceinline__ void cnt_wait(const unsigned* p, unsigned target) {
    unsigned v;
    do {
        asm volatile("ld.acquire.gpu.global.u32 %0, [%1];" : "=r"(v) : "l"(p) : "memory");
    } while (v < target);
}

// ---------------- pack weights + convert x (fused) ----------------
__global__ void pack_kernel(const float* __restrict__ x,
                            const float* __restrict__ Wf, const float* __restrict__ bf,
                            const float* __restrict__ Wi, const float* __restrict__ bi,
                            const float* __restrict__ Wg, const float* __restrict__ bg,
                            const float* __restrict__ Wo, const float* __restrict__ bo,
                            const float* __restrict__ Wr, const float* __restrict__ br) {
    int idx = blockIdx.x * blockDim.x + threadIdx.x;
    int stride = gridDim.x * blockDim.x;
    for (int i = idx; i < NPRE * DD; i += stride) {
        int n = i / DD, d = i - n * DD;
        float v;
        if (n < NG) {
            int hcol = n >> 2, gate = n & 3;
            const float* W = (gate == 0) ? Wf : (gate == 1) ? Wi : (gate == 2) ? Wg : Wo;
            v = W[hcol * DH + d];
        } else {
            v = Wr[(n - NG) * DD + d];
        }
        __nv_bfloat16 hi = __float2bfloat16_rn(v);
        g_Wxhi[i] = hi;
        g_Wxlo[i] = __float2bfloat16_rn(v - __bfloat162float(hi));
    }
    for (int i = idx; i < NG * HH; i += stride) {
        int n = i / HH, k = i - n * HH;
        int hcol = n >> 2, gate = n & 3;
        const float* W = (gate == 0) ? Wf : (gate == 1) ? Wi : (gate == 2) ? Wg : Wo;
        float v = W[hcol * DH + DD + k];
        __nv_bfloat16 hi = __float2bfloat16_rn(v);
        g_Whhi[i] = hi;
        g_Whlo[i] = __float2bfloat16_rn(v - __bfloat162float(hi));
    }
    for (int i = idx; i < NPRE; i += stride) {
        float v;
        if (i < NG) {
            int hcol = i >> 2, gate = i & 3;
            v = (gate == 0) ? bf[hcol] : (gate == 1) ? bi[hcol] : (gate == 2) ? bg[hcol] : bo[hcol];
        } else {
            v = br[i - NG];
        }
        g_bias[i] = v;
    }
    // reset arrival counters (device globals persist across graph replays)
    for (int i = idx; i < 4 * 2 * 32; i += stride) g_cnt[i] = 0u;
    // x -> bf16 hi/lo
    for (size_t i = idx; i < (size_t)NTB * DD; i += stride) {
        float v = x[i];
        __nv_bfloat16 hi = __float2bfloat16_rn(v);
        g_xhi[i] = hi;
        g_xlo[i] = __float2bfloat16_rn(v - __bfloat162float(hi));
    }
}

// ---------------- pre-activation GEMM (HMMA, split bf16), 128x128 tiles ----------------
#define P_ROW 40                         // padded row (bf16 elems) -> 80B stride
#define P_HALF (128 * P_ROW * 2)         // 10240 B per operand-half per stage
#define P_STAGE (4 * P_HALF)             // 40960 B
#define P_SMEM (2 * P_STAGE)             // 81920 B
__global__ void __launch_bounds__(512) pre_gemm_mma() {
    extern __shared__ char sm[];
    const uint32_t smb = smem_u32(sm);
    const int tid = threadIdx.x;
    const int wid = tid >> 5, lane = tid & 31;
    const int mw = wid & 3, nw = wid >> 2;          // warp tile: m32 x n32
    const int mbase = blockIdx.x * 128;             // 20 m-tiles
    const int nbase = blockIdx.y * 128;             // 256 n-tiles

    const int o = tid >> 7, r = tid & 127;
    const __nv_bfloat16* gsrc =
        (o == 0) ? g_Wxhi + (size_t)(mbase + r) * DD :
        (o == 1) ? g_Wxlo + (size_t)(mbase + r) * DD :
        (o == 2) ? g_xhi + (size_t)(nbase + r) * DD :
                   g_xlo + (size_t)(nbase + r) * DD;
    const uint32_t sdst = smb + o * P_HALF + r * 80;

    const int aRow = mw * 32 + ((lane >> 3) & 1) * 8 + (lane & 7);
    const uint32_t aOff = (uint32_t)(aRow * 80 + ((lane >> 4) * 8) * 2);
    const int g8 = lane >> 3;
    uint32_t bOff[2];
#pragma unroll
    for (int pair = 0; pair < 2; pair++) {
        int nRow = nw * 32 + (pair * 2 + (g8 >> 1)) * 8 + (lane & 7);
        bOff[pair] = (uint32_t)(nRow * 80 + ((g8 & 1) * 8) * 2);
    }

    float acc[2][4][4];
#pragma unroll
    for (int i = 0; i < 2; i++)
#pragma unroll
        for (int j = 0; j < 4; j++)
#pragma unroll
            for (int q = 0; q < 4; q++) acc[i][j][q] = 0.f;

    uint4 pf[4];
    auto gload = [&](int chunk) {
        const __nv_bfloat16* p = gsrc + chunk * 32;
#pragma unroll
        for (int j = 0; j < 4; j++) pf[j] = *(const uint4*)(p + j * 8);
    };
    auto sstore = [&](int buf) {
        uint32_t d = sdst + buf * P_STAGE;
#pragma unroll
        for (int j = 0; j < 4; j++)
            *(uint4*)(sm + (d - smb) + j * 16) = pf[j];
    };
    auto do_mma = [&](int buf) {
        uint32_t base = smb + buf * P_STAGE;
#pragma unroll
        for (int kt = 0; kt < 2; kt++) {
            uint32_t ko = kt * 32;
            uint32_t aHi[2][4], aLo[2][4], bHi[4][2], bLo[4][2];
#pragma unroll
            for (int mt = 0; mt < 2; mt++) {
                ldsm4(base + 0 * P_HALF + aOff + mt * 16 * 80 + ko, aHi[mt]);
                ldsm4(base + 1 * P_HALF + aOff + mt * 16 * 80 + ko, aLo[mt]);
            }
#pragma unroll
            for (int pair = 0; pair < 2; pair++) {
                uint32_t t4[4];
                ldsm4(base + 2 * P_HALF + bOff[pair] + ko, t4);
                bHi[pair * 2][0] = t4[0]; bHi[pair * 2][1] = t4[1];
                bHi[pair * 2 + 1][0] = t4[2]; bHi[pair * 2 + 1][1] = t4[3];
                ldsm4(base + 3 * P_HALF + bOff[pair] + ko, t4);
                bLo[pair * 2][0] = t4[0]; bLo[pair * 2][1] = t4[1];
                bLo[pair * 2 + 1][0] = t4[2]; bLo[pair * 2 + 1][1] = t4[3];
            }
#pragma unroll
            for (int mt = 0; mt < 2; mt++)
#pragma unroll
                for (int nt = 0; nt < 4; nt++) {
                    mma16816(acc[mt][nt], aHi[mt], bHi[nt]);
                    mma16816(acc[mt][nt], aHi[mt], bLo[nt]);
                    mma16816(acc[mt][nt], aLo[mt], bHi[nt]);
                }
        }
    };

    gload(0); sstore(0);
    gload(1);
    __syncthreads();
    for (int c = 0; c < 16; c++) {
        if (c + 1 < 16) sstore((c + 1) & 1);
        if (c + 2 < 16) gload(c + 2);
        do_mma(c & 1);
        __syncthreads();
    }

    float* smf = (float*)sm;
#pragma unroll
    for (int mt = 0; mt < 2; mt++)
#pragma unroll
        for (int nt = 0; nt < 4; nt++) {
            int c0 = nw * 32 + nt * 8 + 2 * (lane & 3);
            int r0 = mw * 32 + mt * 16 + (lane >> 2);
            smf[c0 * 132 + r0] = acc[mt][nt][0];
            smf[(c0 + 1) * 132 + r0] = acc[mt][nt][1];
            smf[c0 * 132 + r0 + 8] = acc[mt][nt][2];
            smf[(c0 + 1) * 132 + r0 + 8] = acc[mt][nt][3];
        }
    __syncthreads();
#pragma unroll
    for (int j = 0; j < 8; j++) {
        int idx = j * 512 + tid;
        int c = idx >> 5, seg = idx & 31;
        float4 v = *(const float4*)(smf + c * 132 + seg * 4);
        float4 bv = *(const float4*)&g_bias[mbase + seg * 4];
        v.x += bv.x; v.y += bv.y; v.z += bv.z; v.w += bv.w;
        *(float4*)&g_pre[(size_t)(nbase + c) * NPRE + mbase + seg * 4] = v;
    }
}

// ---------------- persistent LSTM recurrence (HMMA, W resident in smem) ----------------
#define R_WROW 520                       // padded k (bf16) -> 1040B stride
#define R_OWHI 0
#define R_OWLO (64 * R_WROW * 2)         // 66560
#define R_OBHI (2 * 64 * R_WROW * 2)     // 133120
#define R_OBLO (R_OBHI + 16 * R_WROW * 2)
#define R_OACC (R_OBHI + 2 * 16 * R_WROW * 2)
#define R_SMEM (R_OACC + 64 * 17 * 4)    // sAcc[64 rows][16 b] pitch 17
__global__ void __launch_bounds__(256) lstm_persistent(float* __restrict__ out) {
    extern __shared__ char sm[];
    const uint32_t smb = smem_u32(sm);
    const int tid = threadIdx.x;
    const int wid = tid >> 5, lane = tid & 31;
    const int cta = blockIdx.x;
    const int rb = cta & 31;             // 16 hcols: rb*16..
    const int bblk = cta >> 5;           // group: 16 b = bblk*16..
    const int mw = wid & 3;              // m16 tile within 64 rows
    const int nw = wid >> 2;             // b8 tile within 16 b
    const unsigned* cnt0 = &g_cnt[(bblk * 2 + 0) * 32];
    const unsigned* cnt1 = &g_cnt[(bblk * 2 + 1) * 32];
    unsigned* mycnt = &g_cnt[(bblk * 2 + (rb >> 4)) * 32];

    // ---- load resident W slice (packed rows rb*64..+63), full k ----
    for (int i = tid; i < 64 * 64 * 2; i += 256) {
        int hf = i >> 12;
        int rem = i & 4095;
        int r = rem >> 6, s = rem & 63;
        const __nv_bfloat16* src = (hf ? g_Whlo : g_Whhi) + (size_t)(rb * 64 + r) * HH + s * 8;
        *(uint4*)(sm + (hf ? R_OWLO : R_OWHI) + r * (R_WROW * 2) + s * 16) = *(const uint4*)src;
    }

    // ldmatrix lane offsets
    const int aRow = mw * 16 + ((lane >> 3) & 1) * 8 + (lane & 7);
    const uint32_t aOff = (uint32_t)(aRow * (R_WROW * 2) + ((lane >> 4) * 8) * 2);
    const int bRow = nw * 8 + (lane & 7);            // ldsm4 over k32
    const uint32_t bOff = (uint32_t)(bRow * (R_WROW * 2) + ((lane >> 3) * 8) * 2);

    // cell-update lane mapping: hcol contiguous within warp (coalesced I/O)
    const int hc_l = lane & 15;                      // 0..15
    const int bsel = wid * 2 + (lane >> 4);          // 0..15
    const int hcol = rb * 16 + hc_l;
    const int b = bblk * 16 + bsel;
    float* sAcc = (float*)(sm + R_OACC);             // [r 0..63][b 0..15], pitch 17

    float cst = 0.f;
    float hlast = 0.f;

    float4 pg;
    float rv;
    {
        const size_t cb = (size_t)(0 * BB + b) * NPRE;
        pg = __ldcs((const float4*)&g_pre[cb + hcol * 4]);
        rv = __ldcs(&g_pre[cb + NG + hcol]);
    }

    __syncthreads();

    for (int t = 0; t < TT; t++) {
        float gv0 = 0.f, gv1 = 0.f, gv2 = 0.f, gv3 = 0.f;
        if (t > 0) {
            const int rbuf = (t - 1) & 1;
            const unsigned target = (unsigned)t * 16u;
            // chunk c covers k = c*256.. , produced by half-group c; poll + stage per half
#pragma unroll
            for (int c = 0; c < 2; c++) {
                cnt_wait(c == 0 ? cnt0 : cnt1, target);
#pragma unroll
                for (int j = 0; j < 4; j++) {
                    int i = tid + j * 256;           // 0..1023
                    int hf = i >> 9;
                    int rem = i & 511;
                    int r = rem >> 5, s = (rem & 31) + c * 32;
                    const void* src = (const void*)((hf ? g_hlo : g_hhi) + rbuf * BB * HH +
                                                    (size_t)(bblk * 16 + r) * HH + s * 8);
                    cp_async16(smb + (hf ? R_OBLO : R_OBHI) + r * (R_WROW * 2) + s * 16, src);
                }
                asm volatile("cp.async.commit_group;" ::: "memory");
            }

            float aA0[4] = {}, aB0[4] = {}, aC0[4] = {};
            float aA1[4] = {}, aB1[4] = {}, aC1[4] = {};

            asm volatile("cp.async.wait_group 1;" ::: "memory");
            __syncthreads();
#pragma unroll 4
            for (int kt2 = 0; kt2 < 8; kt2++) {
                uint32_t ko = kt2 * 64;
                uint32_t aHi0[4], aHi1[4], aLo0[4], aLo1[4], bH[4], bL[4];
                ldsm4(smb + R_OWHI + aOff + ko, aHi0);
                ldsm4(smb + R_OWHI + aOff + ko + 32, aHi1);
                ldsm4(smb + R_OWLO + aOff + ko, aLo0);
                ldsm4(smb + R_OWLO + aOff + ko + 32, aLo1);
                ldsm4(smb + R_OBHI + bOff + ko, bH);
                ldsm4(smb + R_OBLO + bOff + ko, bL);
                mma16816(aA0, aHi0, bH);
                mma16816(aB0, aHi0, bL);
                mma16816(aC0, aLo0, bH);
                mma16816(aA1, aHi1, bH + 2);
                mma16816(aB1, aHi1, bL + 2);
                mma16816(aC1, aLo1, bH + 2);
            }
            asm volatile("cp.async.wait_group 0;" ::: "memory");
            __syncthreads();
#pragma unroll 4
            for (int kt2 = 8; kt2 < 16; kt2++) {
                uint32_t ko = kt2 * 64;
                uint32_t aHi0[4], aHi1[4], aLo0[4], aLo1[4], bH[4], bL[4];
                ldsm4(smb + R_OWHI + aOff + ko, aHi0);
                ldsm4(smb + R_OWHI + aOff + ko + 32, aHi1);
                ldsm4(smb + R_OWLO + aOff + ko, aLo0);
                ldsm4(smb + R_OWLO + aOff + ko + 32, aLo1);
                ldsm4(smb + R_OBHI + bOff + ko, bH);
                ldsm4(smb + R_OBLO + bOff + ko, bL);
                mma16816(aA0, aHi0, bH);
                mma16816(aB0, aHi0, bL);
                mma16816(aC0, aLo0, bH);
                mma16816(aA1, aHi1, bH + 2);
                mma16816(aB1, aHi1, bL + 2);
                mma16816(aC1, aLo1, bH + 2);
            }
            {
                int r0 = mw * 16 + (lane >> 2);
                int c0 = nw * 8 + 2 * (lane & 3);
                sAcc[r0 * 17 + c0]           = aA0[0] + aB0[0] + aC0[0] + aA1[0] + aB1[0] + aC1[0];
                sAcc[r0 * 17 + c0 + 1]       = aA0[1] + aB0[1] + aC0[1] + aA1[1] + aB1[1] + aC1[1];
                sAcc[(r0 + 8) * 17 + c0]     = aA0[2] + aB0[2] + aC0[2] + aA1[2] + aB1[2] + aC1[2];
                sAcc[(r0 + 8) * 17 + c0 + 1] = aA0[3] + aB0[3] + aC0[3] + aA1[3] + aB1[3] + aC1[3];
            }
            __syncthreads();
            gv0 = sAcc[(hc_l * 4 + 0) * 17 + bsel];
            gv1 = sAcc[(hc_l * 4 + 1) * 17 + bsel];
            gv2 = sAcc[(hc_l * 4 + 2) * 17 + bsel];
            gv3 = sAcc[(hc_l * 4 + 3) * 17 + bsel];
        }

        // consume pg/rv, then immediately prefetch t+1 (overlaps transcendentals + publish)
        float fp = pg.x + gv0, ip = pg.y + gv1, gp = pg.z + gv2, op = pg.w + gv3;
        float rvc = rv;
        if (t + 1 < TT) {
            const size_t cb = (size_t)((t + 1) * BB + b) * NPRE;
            pg = __ldcs((const float4*)&g_pre[cb + hcol * 4]);
            rv = __ldcs(&g_pre[cb + NG + hcol]);
        }

        float f = fast_sigmoid(fp);
        float ii = fast_sigmoid(ip);
        float gg = fast_tanh(gp);
        float oo = fast_sigmoid(op);
        cst = f * cst + ii * gg;
        float h = oo * fast_tanh(cst) + rvc;
        hlast = h;

        const int wbuf = t & 1;
        __nv_bfloat16 hhi = __float2bfloat16_rn(h);
        __nv_bfloat16 hlo = __float2bfloat16_rn(h - __bfloat162float(hhi));
        {
            unsigned short uhi = *(unsigned short*)&hhi;
            unsigned short ulo = *(unsigned short*)&hlo;
            asm volatile("st.global.cg.u16 [%0], %1;"
                         :: "l"(&g_hhi[wbuf * BB * HH + b * HH + hcol]), "h"(uhi) : "memory");
            asm volatile("st.global.cg.u16 [%0], %1;"
                         :: "l"(&g_hlo[wbuf * BB * HH + b * HH + hcol]), "h"(ulo) : "memory");
        }

        if (t + 1 < TT) {
            __syncthreads();             // order this CTA's h stores before the release
            if (tid == 0) {
                unsigned d;
                asm volatile("atom.release.gpu.global.add.u32 %0, [%1], 1;"
                             : "=r"(d) : "l"(mycnt) : "memory");
            }
            // off-critical-path:
            out[(size_t)t * BB * HH + (size_t)b * HH + hcol] = h;
        } else {
            out[(size_t)t * BB * HH + (size_t)b * HH + hcol] = h;
        }
    }

    out[(size_t)TT * BB * HH + (size_t)b * HH + hcol] = hlast;
    out[(size_t)TT * BB * HH + BB * HH + (size_t)b * HH + hcol] = cst;
}

extern "C" void kernel_launch(void* const* d_in, const int* in_sizes, int n_in,
                              void* d_out, int out_size) {
    const float* x  = (const float*)d_in[0];
    const float* Wf = (const float*)d_in[1];
    const float* bf = (const float*)d_in[2];
    const float* Wi = (const float*)d_in[3];
    const float* bi = (const float*)d_in[4];
    const float* Wg = (const float*)d_in[5];
    const float* bg = (const float*)d_in[6];
    const float* Wo = (const float*)d_in[7];
    const float* bo = (const float*)d_in[8];
    const float* Wr = (const float*)d_in[9];
    const float* br = (const float*)d_in[10];
    float* out = (float*)d_out;

    static int inited = 0;
    if (!inited) {
        cudaFuncSetAttribute(pre_gemm_mma, cudaFuncAttributeMaxDynamicSharedMemorySize, P_SMEM);
        cudaFuncSetAttribute(lstm_persistent, cudaFuncAttributeMaxDynamicSharedMemorySize, R_SMEM);
        inited = 1;
    }

    pack_kernel<<<512, 256>>>(x, Wf, bf, Wi, bi, Wg, bg, Wo, bo, Wr, br);
    pre_gemm_mma<<<dim3(NPRE / 128, NTB / 128), 512, P_SMEM>>>();
    lstm_persistent<<<NCTA, 256, R_SMEM>>>(out);
}